// round 13
// baseline (speedup 1.0000x reference)
#include <cuda_runtime.h>
#include <cstdint>

#define LN 1000000
#define DN 16
#define KN 8
#define WN 64
#define TOUT 176
#define NROWS 192               /* j rows: covers u+b <= 175+15 = 190 */
#define THREADS 256
#define XW 240                  /* TOUT + 64 */
#define XSTR 241
#define YSTR 196
#define NTILES ((LN + TOUT - 1) / TOUT)   /* 5682 */
#define GRID 152

/* smem layout */
#define OFF_AH 0                /* 2048 u32 = 8192 B, per-lane fragment order */
#define OFF_AL 8192
#define OFF_BH 16384            /* 8 slices x 196 uint2 = 12544 B */
#define OFF_BL 28928
#define OFF_YS 41472            /* 128*196*4 = 100352 B; aliased as x staging */
#define SMEM_BYTES 141824

#define BSLICE 196              /* padded uint2 stride per (kc,t) slice: 32B bank skew */

static __device__ uint32_t g_Ah[2048];   /* [mt][kc][lane][reg] packed s8 quads */
static __device__ uint32_t g_Al[2048];

__device__ __forceinline__ void mma_s8(int* c, uint32_t a0, uint32_t a1, uint32_t a2,
                                       uint32_t a3, uint32_t b0, uint32_t b1) {
    asm volatile("mma.sync.aligned.m16n8k32.row.col.s32.s8.s8.s32 "
                 "{%0,%1,%2,%3}, {%4,%5,%6,%7}, {%8,%9}, {%0,%1,%2,%3};"
                 : "+r"(c[0]), "+r"(c[1]), "+r"(c[2]), "+r"(c[3])
                 : "r"(a0), "r"(a1), "r"(a2), "r"(a3), "r"(b0), "r"(b1));
}

__device__ __forceinline__ uint32_t pk4(int v0, int v1, int v2, int v3) {
    return (uint32_t)(v0 & 255) | ((uint32_t)(v1 & 255) << 8) |
           ((uint32_t)(v2 & 255) << 16) | ((uint32_t)(v3 & 255) << 24);
}

__device__ __forceinline__ void qsplit_x(float v, int& h, int& l) {
    int xi = __float2int_rn(v * 2048.0f);           /* scale 2^11 */
    xi = xi < -16256 ? -16256 : (xi > 16256 ? 16256 : xi);
    l = ((xi + 64) & 127) - 64;                     /* base-128 digits */
    h = (xi - l) >> 7;
}

/* A[(kf,b)][k=16a+d] = P[kf,d,16a+b]; quantize scale 2^13, split digits,
   store packed s8 quads in exact m16n8k32 per-lane fragment order. */
__global__ void prep_A(const float* __restrict__ P) {
    int idx = blockIdx.x * blockDim.x + threadIdx.x;   /* 2048 */
    int reg = idx & 3, lane = (idx >> 2) & 31, kc = (idx >> 7) & 1, mt = idx >> 8;
    int grp = lane >> 2, tg = lane & 3;
    int m = mt * 16 + grp + (reg & 1) * 8;
    int k0 = kc * 32 + tg * 4 + (reg >> 1) * 16;
    int kf = m >> 4, b = m & 15;
    uint32_t hi = 0, lo = 0;
    #pragma unroll
    for (int i = 0; i < 4; i++) {
        int k = k0 + i, a = k >> 4, d = k & 15;
        float v = P[kf * (DN * WN) + d * WN + a * 16 + b];
        int pi = __float2int_rn(v * 8192.0f);          /* [0, 8192] */
        int pl = ((pi + 64) & 127) - 64;
        int ph = (pi - pl) >> 7;                       /* [0, 64] */
        hi |= (uint32_t)(ph & 255) << (8 * i);
        lo |= (uint32_t)(pl & 255) << (8 * i);
    }
    g_Ah[idx] = hi;
    g_Al[idx] = lo;
}

extern __shared__ unsigned char smem[];

__device__ __forceinline__ void prefetch_x(const float* __restrict__ x, int t, int tid,
                                           float* __restrict__ xr) {
    const int t0 = t * TOUT;
    #pragma unroll
    for (int j = 0; j < 15; j++) {
        int i = tid + j * THREADS;            /* 3840 = 16*240 */
        int d = i / XW, c = i - d * XW;
        int g = t0 - 31 + c;
        g = g < 0 ? 0 : (g > LN - 1 ? LN - 1 : g);
        xr[j] = __ldg(x + (size_t)d * LN + g);
    }
}

__global__ void __launch_bounds__(THREADS, 1)
fullscan_imma(const float* __restrict__ x, float* __restrict__ out) {
    const int tid = threadIdx.x;
    const int wid = tid >> 5;
    const int lid = tid & 31;

    /* copy packed A hi/lo into smem (16 KB) */
    {
        const uint4* gh = (const uint4*)g_Ah;
        const uint4* gl = (const uint4*)g_Al;
        uint4* sh = (uint4*)(smem + OFF_AH);
        uint4* sl = (uint4*)(smem + OFF_AL);
        #pragma unroll
        for (int i = 0; i < 2; i++) { sh[tid + i * THREADS] = gh[tid + i * THREADS]; }
        #pragma unroll
        for (int i = 0; i < 2; i++) { sl[tid + i * THREADS] = gl[tid + i * THREADS]; }
    }

    float* ys = (float*)(smem + OFF_YS);
    float* xs = (float*)(smem + OFF_YS);   /* staging aliases ys space */

    const int grp = lid >> 2, tg = lid & 3;   /* fragment lane decomposition */
    const int n0w = wid * 24;                 /* warp's 24-col N slice */
    const float C1 = 0.0009765625f;           /* 2^-10 */
    const float C2 = 7.62939453125e-6f;       /* 2^-17 */

    float xr[15];
    prefetch_x(x, blockIdx.x, tid, xr);

    for (int t = blockIdx.x; t < NTILES; t += GRID) {
        const int t0 = t * TOUT;

        /* stage x tile from prefetched regs: xs[d][c], c in [0,240) */
        #pragma unroll
        for (int j = 0; j < 15; j++) {
            int i = tid + j * THREADS;
            int d = i / XW, c = i - d * XW;
            xs[d * XSTR + c] = xr[j];
        }
        __syncthreads();

        /* build B fragment quads: slice (kc,t) holds {b0,b1} per j.
           b0: k = kc*32 + t*4 + i  (a = 2kc, d = 4t+i) -> x col j + 32kc
           b1: k + 16               (a = 2kc+1)         -> x col j + 32kc + 16 */
        #pragma unroll
        for (int it = 0; it < 6; it++) {
            int idx = tid + it * THREADS;          /* [0, 1536) */
            int tt = idx & 3, kc = (idx >> 2) & 1, j = idx >> 3;
            const float* xp = xs + (tt * 4) * XSTR + (j + 32 * kc);
            int h[8], l[8];
            #pragma unroll
            for (int i = 0; i < 4; i++) qsplit_x(xp[i * XSTR], h[i], l[i]);
            #pragma unroll
            for (int i = 0; i < 4; i++) qsplit_x(xp[i * XSTR + 16], h[4 + i], l[4 + i]);
            uint32_t bh0 = pk4(h[0], h[1], h[2], h[3]);
            uint32_t bh1 = pk4(h[4], h[5], h[6], h[7]);
            uint32_t bl0 = pk4(l[0], l[1], l[2], l[3]);
            uint32_t bl1 = pk4(l[4], l[5], l[6], l[7]);
            int sl = (kc * 4 + tt) * BSLICE + j;
            *(uint2*)(smem + OFF_BH + sl * 8) = make_uint2(bh0, bh1);
            *(uint2*)(smem + OFF_BL + sl * 8) = make_uint2(bl0, bl1);
        }
        __syncthreads();

        /* prefetch next tile's x (LDG latency hides under the MMA loop) */
        {
            int tn = t + GRID;
            prefetch_x(x, tn < NTILES ? tn : 0, tid, xr);
        }

        const int quad = lid >> 2, ql = lid & 3;

        #pragma unroll
        for (int half = 0; half < 2; half++) {
            int hh[4][3][4], cr[4][3][4];
            #pragma unroll
            for (int mt4 = 0; mt4 < 4; mt4++)
                #pragma unroll
                for (int nt = 0; nt < 3; nt++)
                    #pragma unroll
                    for (int r = 0; r < 4; r++) { hh[mt4][nt][r] = 0; cr[mt4][nt][r] = 0; }

            #pragma unroll
            for (int kc = 0; kc < 2; kc++) {
                uint32_t bh0[3], bh1[3], bl0[3], bl1[3];
                #pragma unroll
                for (int nt = 0; nt < 3; nt++) {
                    int sl = (kc * 4 + tg) * BSLICE + (n0w + nt * 8 + grp);
                    uint2 vh = *(const uint2*)(smem + OFF_BH + sl * 8);
                    uint2 vl = *(const uint2*)(smem + OFF_BL + sl * 8);
                    bh0[nt] = vh.x; bh1[nt] = vh.y;
                    bl0[nt] = vl.x; bl1[nt] = vl.y;
                }
                #pragma unroll
                for (int mt4 = 0; mt4 < 4; mt4++) {
                    int mt = half * 4 + mt4;
                    int addr = ((mt * 2 + kc) * 32 + lid) * 16;
                    uint4 ah = *(const uint4*)(smem + OFF_AH + addr);
                    uint4 al = *(const uint4*)(smem + OFF_AL + addr);
                    #pragma unroll
                    for (int nt = 0; nt < 3; nt++) {
                        mma_s8(hh[mt4][nt], ah.x, ah.y, ah.z, ah.w, bh0[nt], bh1[nt]);
                        mma_s8(cr[mt4][nt], ah.x, ah.y, ah.z, ah.w, bl0[nt], bl1[nt]);
                        mma_s8(cr[mt4][nt], al.x, al.y, al.z, al.w, bh0[nt], bh1[nt]);
                    }
                }
            }

            /* fold to fp32 and store this m-half to ys */
            #pragma unroll
            for (int mt4 = 0; mt4 < 4; mt4++) {
                #pragma unroll
                for (int nt = 0; nt < 3; nt++) {
                    int r0 = (half * 4 + mt4) * 16 + quad;
                    int c0 = n0w + nt * 8 + ql * 2;
                    float v0 = fmaf((float)hh[mt4][nt][0], C1, (float)cr[mt4][nt][0] * C2);
                    float v1 = fmaf((float)hh[mt4][nt][1], C1, (float)cr[mt4][nt][1] * C2);
                    float v2 = fmaf((float)hh[mt4][nt][2], C1, (float)cr[mt4][nt][2] * C2);
                    float v3 = fmaf((float)hh[mt4][nt][3], C1, (float)cr[mt4][nt][3] * C2);
                    *(float2*)(ys + r0 * YSTR + c0)       = make_float2(v0, v1);
                    *(float2*)(ys + (r0 + 8) * YSTR + c0) = make_float2(v2, v3);
                }
            }
        }
        __syncthreads();

        /* diagonal b-sum: y[k, t0+u] = sum_b ys[k*16+b][u+b] */
        for (int o = tid; o < KN * TOUT; o += THREADS) {
            int k = o / TOUT, u = o - k * TOUT;
            if (t0 + u < LN) {
                const float* yb = ys + (k * 16) * YSTR + u;
                float s = 0.f;
                #pragma unroll
                for (int b = 0; b < 16; b++) s += yb[b * YSTR + b];
                out[(size_t)k * LN + t0 + u] = s;
            }
        }
        __syncthreads();
    }
}

/* exact reference boundary semantics in fp32 (overwrites first 31 / last 32 cols) */
__global__ void fullscan_boundary(const float* __restrict__ x, const float* __restrict__ P,
                                  float* __restrict__ out) {
    __shared__ float tl[KN][WN];
    __shared__ float tr[KN][WN];
    int tid = threadIdx.x;          /* 512 threads */
    int k = tid >> 6, m = tid & 63;
    float sl = 0.f, sr = 0.f;
    #pragma unroll
    for (int d = 0; d < DN; d++) {
        float p = P[k * (DN * WN) + d * WN + m];
        sl += x[(size_t)d * LN + m] * p;
        sr += x[(size_t)d * LN + (LN - WN) + m] * p;
    }
    tl[k][m] = sl; tr[k][m] = sr;
    __syncthreads();
    if (m < 31) {
        float s = 0.f;
        for (int mm = 0; mm <= 32 + m; mm++) s += tl[k][mm];
        out[(size_t)k * LN + m] = s;
    }
    if (m < 32) {
        float s = 0.f;
        for (int mm = m + 1; mm < WN; mm++) s += tr[k][mm];
        out[(size_t)k * LN + (LN - 32) + m] = s;
    }
}

extern "C" void kernel_launch(void* const* d_in, const int* in_sizes, int n_in,
                              void* d_out, int out_size) {
    const float* x = (const float*)d_in[0];
    const float* P = (const float*)d_in[1];
    float* out = (float*)d_out;

    cudaFuncSetAttribute(fullscan_imma, cudaFuncAttributeMaxDynamicSharedMemorySize, SMEM_BYTES);

    prep_A<<<8, 256>>>(P);
    fullscan_imma<<<GRID, THREADS, SMEM_BYTES>>>(x, out);
    fullscan_boundary<<<1, 512>>>(x, P, out);
}

// round 14
// speedup vs baseline: 2.4407x; 2.4407x over previous
#include <cuda_runtime.h>
#include <cuda_fp16.h>
#include <cstdint>

#define LN 1000000
#define DN 16
#define KN 8
#define WN 64
#define TOUT 176
#define NROWS 192               /* j rows: covers u+b <= 175+15 = 190 */
#define THREADS 256
#define XW 240                  /* TOUT + 64 */
#define XSTR 241
#define YSTR 196
#define NTILES ((LN + TOUT - 1) / TOUT)   /* 5682 */
#define GRID 152

/* smem byte offsets (1024-aligned bases for clean SW128) */
#define OFF_A  0                /* 128*128 B = 16384 */
#define OFF_BH 16384            /* 192*128 = 24576 B */
#define OFF_BL 40960
#define OFF_YS 65536            /* 128*196*4 = 100352 B; aliased as x staging */
#define SMEM_BYTES 165888

#define SW128(o) ((o) ^ (((o) >> 3) & 0x70))

static __device__ __half g_A[8192];   /* [m=128][col=64], col=16a+d, f16(P), pre-swizzled */

__device__ __forceinline__ uint32_t smem_u32(const void* p) {
    uint32_t a;
    asm("{ .reg .u64 t; cvta.to.shared.u64 t, %1; cvt.u32.u64 %0, t; }" : "=r"(a) : "l"(p));
    return a;
}

__device__ __forceinline__ void ldsm_x4(uint32_t& r0, uint32_t& r1, uint32_t& r2, uint32_t& r3,
                                        uint32_t addr) {
    asm volatile("ldmatrix.sync.aligned.m8n8.x4.shared.b16 {%0,%1,%2,%3}, [%4];"
                 : "=r"(r0), "=r"(r1), "=r"(r2), "=r"(r3) : "r"(addr));
}
__device__ __forceinline__ void ldsm_x2(uint32_t& r0, uint32_t& r1, uint32_t addr) {
    asm volatile("ldmatrix.sync.aligned.m8n8.x2.shared.b16 {%0,%1}, [%2];"
                 : "=r"(r0), "=r"(r1) : "r"(addr));
}
__device__ __forceinline__ void mma16816(float* c, uint32_t a0, uint32_t a1, uint32_t a2,
                                         uint32_t a3, uint32_t b0, uint32_t b1) {
    asm volatile("mma.sync.aligned.m16n8k16.row.col.f32.f16.f16.f32 "
                 "{%0,%1,%2,%3}, {%4,%5,%6,%7}, {%8,%9}, {%0,%1,%2,%3};"
                 : "+f"(c[0]), "+f"(c[1]), "+f"(c[2]), "+f"(c[3])
                 : "r"(a0), "r"(a1), "r"(a2), "r"(a3), "r"(b0), "r"(b1));
}

/* A[(k,b)][col=16a+d] = f16(P[k,d,16a+b]), pre-swizzled */
__global__ void prep_A(const float* __restrict__ P) {
    int idx = blockIdx.x * blockDim.x + threadIdx.x;   /* 8192 */
    int m = idx >> 6, col = idx & 63;
    int k = m >> 4, b = m & 15, a = col >> 4, d = col & 15;
    float v = P[k * (DN * WN) + d * WN + 16 * a + b];
    uint32_t off = SW128((uint32_t)(m * 128 + col * 2));
    g_A[off >> 1] = __float2half(v);
}

extern __shared__ unsigned char smem[];

__device__ __forceinline__ void prefetch_x(const float* __restrict__ x, int t, int tid,
                                           float* __restrict__ xr) {
    const int t0 = t * TOUT;
    #pragma unroll
    for (int j = 0; j < 15; j++) {
        int i = tid + j * THREADS;            /* 3840 = 16*240 */
        int d = i / XW, c = i - d * XW;
        int g = t0 - 31 + c;
        g = g < 0 ? 0 : (g > LN - 1 ? LN - 1 : g);
        xr[j] = __ldg(x + (size_t)d * LN + g);
    }
}

__global__ void __launch_bounds__(THREADS, 1)
fullscan_mma(const float* __restrict__ x, float* __restrict__ out) {
    const int tid = threadIdx.x;
    const int wid = tid >> 5;
    const int lid = tid & 31;
    const uint32_t sbase = smem_u32(smem);

    /* copy pre-swizzled f16 A into smem (16 KB) */
    {
        const uint4* ga = (const uint4*)g_A;
        uint4* sa = (uint4*)(smem + OFF_A);
        #pragma unroll
        for (int i = 0; i < 4; i++) { sa[tid + i * THREADS] = ga[tid + i * THREADS]; }
    }

    float* ys = (float*)(smem + OFF_YS);
    float* xs = (float*)(smem + OFF_YS);   /* staging aliases ys space */

    /* per-lane fragment address components (PTX ISA ldmatrix lane->address map) */
    const int arow = lid & 15;             /* A: row within m-tile */
    const int acol8 = (lid >> 4) << 3;     /* A: k-half (0 or 8) */
    const int bl16 = lid & 15;
    const int brow = bl16 & 7;             /* B: row within n-tile */
    const int bcol8 = (bl16 >> 3) << 3;    /* B: k-half (0 or 8) */
    const int n0w = wid * 24;              /* warp's 24-col N slice */

    float xr[15];
    prefetch_x(x, blockIdx.x, tid, xr);

    for (int t = blockIdx.x; t < NTILES; t += GRID) {
        const int t0 = t * TOUT;

        /* stage x tile from prefetched regs: xs[d][c], c in [0,240) */
        #pragma unroll
        for (int j = 0; j < 15; j++) {
            int i = tid + j * THREADS;
            int d = i / XW, c = i - d * XW;
            xs[d * XSTR + c] = xr[j];
        }
        __syncthreads();

        /* build B hi/lo (two-term f16 expansion of x):
           B[j][col=16a+d] = xs[d][j+16a]; 8 cols -> one STS.128 */
        for (int i = tid; i < NROWS * 8; i += THREADS) {
            int j = i >> 3, g = i & 7;
            int a = g >> 1, d0 = (g & 1) * 8;
            const float* xp = xs + d0 * XSTR + (j + 16 * a);
            uint32_t hv[4], lv[4];
            #pragma unroll
            for (int s = 0; s < 4; s++) {
                float v0 = xp[(2 * s) * XSTR];
                float v1 = xp[(2 * s + 1) * XSTR];
                __half h0 = __float2half(v0);
                __half h1 = __float2half(v1);
                __half l0 = __float2half(v0 - __half2float(h0));
                __half l1 = __float2half(v1 - __half2float(h1));
                hv[s] = (uint32_t)__half_as_ushort(h0) | ((uint32_t)__half_as_ushort(h1) << 16);
                lv[s] = (uint32_t)__half_as_ushort(l0) | ((uint32_t)__half_as_ushort(l1) << 16);
            }
            uint32_t off = SW128((uint32_t)(j * 128 + g * 16));
            *(uint4*)(smem + OFF_BH + off) = make_uint4(hv[0], hv[1], hv[2], hv[3]);
            *(uint4*)(smem + OFF_BL + off) = make_uint4(lv[0], lv[1], lv[2], lv[3]);
        }
        __syncthreads();

        /* prefetch next tile's x (LDG latency hides under the MMA loop) */
        {
            int tn = t + GRID;
            prefetch_x(x, tn < NTILES ? tn : 0, tid, xr);
        }

        /* warp GEMM: Y'[0:128][n0w:n0w+24] = p16·xh + p16·xl, 2 passes */
        float acc[8][3][4];
        #pragma unroll
        for (int mt = 0; mt < 8; mt++)
            #pragma unroll
            for (int nt = 0; nt < 3; nt++)
                #pragma unroll
                for (int r = 0; r < 4; r++) acc[mt][nt][r] = 0.f;

        #pragma unroll 1
        for (int split = 0; split < 2; split++) {
            const uint32_t aBase = sbase + OFF_A;
            const uint32_t bBase = sbase + ((split == 1) ? OFF_BL : OFF_BH);
            #pragma unroll
            for (int kc = 0; kc < 4; kc++) {
                const int k0 = kc * 16;
                uint32_t b0[3], b1[3];
                #pragma unroll
                for (int nt = 0; nt < 3; nt++) {
                    uint32_t off = (uint32_t)((n0w + nt * 8 + brow) * 128 + (k0 + bcol8) * 2);
                    ldsm_x2(b0[nt], b1[nt], bBase + SW128(off));
                }
                #pragma unroll
                for (int mt = 0; mt < 8; mt++) {
                    uint32_t a0, a1, a2, a3;
                    uint32_t off = (uint32_t)((mt * 16 + arow) * 128 + (k0 + acol8) * 2);
                    ldsm_x4(a0, a1, a2, a3, aBase + SW128(off));
                    #pragma unroll
                    for (int nt = 0; nt < 3; nt++)
                        mma16816(acc[mt][nt], a0, a1, a2, a3, b0[nt], b1[nt]);
                }
            }
        }

        __syncthreads();   /* B consumed; ys region (aliases xs) free to write */

        /* epilogue: fragments -> ys[m][j] */
        {
            const int quad = lid >> 2, ql = lid & 3;
            #pragma unroll
            for (int mt = 0; mt < 8; mt++) {
                #pragma unroll
                for (int nt = 0; nt < 3; nt++) {
                    int r0 = mt * 16 + quad;
                    int c0 = n0w + nt * 8 + ql * 2;
                    *(float2*)(ys + r0 * YSTR + c0)       = make_float2(acc[mt][nt][0], acc[mt][nt][1]);
                    *(float2*)(ys + (r0 + 8) * YSTR + c0) = make_float2(acc[mt][nt][2], acc[mt][nt][3]);
                }
            }
        }
        __syncthreads();

        /* diagonal b-sum: y[k, t0+u] = sum_b ys[k*16+b][u+b] */
        for (int o = tid; o < KN * TOUT; o += THREADS) {
            int k = o / TOUT, u = o - k * TOUT;
            if (t0 + u < LN) {
                const float* yb = ys + (k * 16) * YSTR + u;
                float s = 0.f;
                #pragma unroll
                for (int b = 0; b < 16; b++) s += yb[b * YSTR + b];
                out[(size_t)k * LN + t0 + u] = s;
            }
        }
        __syncthreads();
    }
}

/* exact reference boundary semantics in fp32 (overwrites first 31 / last 32 cols) */
__global__ void fullscan_boundary(const float* __restrict__ x, const float* __restrict__ P,
                                  float* __restrict__ out) {
    __shared__ float tl[KN][WN];
    __shared__ float tr[KN][WN];
    int tid = threadIdx.x;          /* 512 threads */
    int k = tid >> 6, m = tid & 63;
    float sl = 0.f, sr = 0.f;
    #pragma unroll
    for (int d = 0; d < DN; d++) {
        float p = P[k * (DN * WN) + d * WN + m];
        sl += x[(size_t)d * LN + m] * p;
        sr += x[(size_t)d * LN + (LN - WN) + m] * p;
    }
    tl[k][m] = sl; tr[k][m] = sr;
    __syncthreads();
    if (m < 31) {
        float s = 0.f;
        for (int mm = 0; mm <= 32 + m; mm++) s += tl[k][mm];
        out[(size_t)k * LN + m] = s;
    }
    if (m < 32) {
        float s = 0.f;
        for (int mm = m + 1; mm < WN; mm++) s += tr[k][mm];
        out[(size_t)k * LN + (LN - 32) + m] = s;
    }
}

extern "C" void kernel_launch(void* const* d_in, const int* in_sizes, int n_in,
                              void* d_out, int out_size) {
    const float* x = (const float*)d_in[0];
    const float* P = (const float*)d_in[1];
    float* out = (float*)d_out;

    cudaFuncSetAttribute(fullscan_mma, cudaFuncAttributeMaxDynamicSharedMemorySize, SMEM_BYTES);

    prep_A<<<32, 256>>>(P);
    fullscan_mma<<<GRID, THREADS, SMEM_BYTES>>>(x, out);
    fullscan_boundary<<<1, 512>>>(x, P, out);
}

// round 17
// speedup vs baseline: 3.2537x; 1.3331x over previous
#include <cuda_runtime.h>
#include <cuda_fp16.h>
#include <cstdint>

#define LN 1000000
#define DN 16
#define KN 8
#define WN 64
#define TOUT 176
#define NROWS 192               /* j rows: covers u+b <= 175+15 = 190 */
#define THREADS 256
#define XW 240                  /* TOUT + 64 */
#define XSTR 241
#define YSTR 196
#define NTILES ((LN + TOUT - 1) / TOUT)   /* 5682 */
#define GRID 152

/* smem byte offsets (1024-aligned bases for clean SW128) */
#define OFF_A  0                /* 128*128 B = 16384 */
#define OFF_B  16384            /* 192*128 = 24576 B */
#define OFF_YS 40960            /* 128*196*4 = 100352 B; aliased as x staging */
#define SMEM_BYTES 141312

#define SW128(o) ((o) ^ (((o) >> 3) & 0x70))

static __device__ __half g_A[8192];   /* [m=128][col=64], col=16a+d, f16(P), pre-swizzled */

__device__ __forceinline__ uint32_t smem_u32(const void* p) {
    uint32_t a;
    asm("{ .reg .u64 t; cvta.to.shared.u64 t, %1; cvt.u32.u64 %0, t; }" : "=r"(a) : "l"(p));
    return a;
}

__device__ __forceinline__ void ldsm_x4(uint32_t& r0, uint32_t& r1, uint32_t& r2, uint32_t& r3,
                                        uint32_t addr) {
    asm volatile("ldmatrix.sync.aligned.m8n8.x4.shared.b16 {%0,%1,%2,%3}, [%4];"
                 : "=r"(r0), "=r"(r1), "=r"(r2), "=r"(r3) : "r"(addr));
}
__device__ __forceinline__ void ldsm_x2(uint32_t& r0, uint32_t& r1, uint32_t addr) {
    asm volatile("ldmatrix.sync.aligned.m8n8.x2.shared.b16 {%0,%1}, [%2];"
                 : "=r"(r0), "=r"(r1) : "r"(addr));
}
__device__ __forceinline__ void mma16816(float* c, uint32_t a0, uint32_t a1, uint32_t a2,
                                         uint32_t a3, uint32_t b0, uint32_t b1) {
    asm volatile("mma.sync.aligned.m16n8k16.row.col.f32.f16.f16.f32 "
                 "{%0,%1,%2,%3}, {%4,%5,%6,%7}, {%8,%9}, {%0,%1,%2,%3};"
                 : "+f"(c[0]), "+f"(c[1]), "+f"(c[2]), "+f"(c[3])
                 : "r"(a0), "r"(a1), "r"(a2), "r"(a3), "r"(b0), "r"(b1));
}

/* A[(k,b)][col=16a+d] = f16(P[k,d,16a+b]), pre-swizzled */
__global__ void prep_A(const float* __restrict__ P) {
    int idx = blockIdx.x * blockDim.x + threadIdx.x;   /* 8192 */
    int m = idx >> 6, col = idx & 63;
    int k = m >> 4, b = m & 15, a = col >> 4, d = col & 15;
    float v = P[k * (DN * WN) + d * WN + 16 * a + b];
    uint32_t off = SW128((uint32_t)(m * 128 + col * 2));
    g_A[off >> 1] = __float2half(v);
}

extern __shared__ unsigned char smem[];

__device__ __forceinline__ void prefetch_x(const float* __restrict__ x, int t, int tid,
                                           float* __restrict__ xr) {
    const int t0 = t * TOUT;
    #pragma unroll
    for (int j = 0; j < 15; j++) {
        int i = tid + j * THREADS;            /* 3840 = 16*240 */
        int d = i / XW, c = i - d * XW;
        int g = t0 - 31 + c;
        g = g < 0 ? 0 : (g > LN - 1 ? LN - 1 : g);
        xr[j] = __ldg(x + (size_t)d * LN + g);
    }
}

__global__ void __launch_bounds__(THREADS, 1)
fullscan_mma(const float* __restrict__ x, float* __restrict__ out) {
    const int tid = threadIdx.x;
    const int wid = tid >> 5;
    const int lid = tid & 31;
    const uint32_t sbase = smem_u32(smem);

    /* copy pre-swizzled f16 A into smem (16 KB) */
    {
        const uint4* ga = (const uint4*)g_A;
        uint4* sa = (uint4*)(smem + OFF_A);
        #pragma unroll
        for (int i = 0; i < 4; i++) { sa[tid + i * THREADS] = ga[tid + i * THREADS]; }
    }

    float* ys = (float*)(smem + OFF_YS);
    float* xs = (float*)(smem + OFF_YS);   /* staging aliases ys space */

    /* per-lane fragment address components (PTX ISA ldmatrix lane->address map) */
    const int arow = lid & 15;             /* A: row within m-tile */
    const int acol8 = (lid >> 4) << 3;     /* A: k-half (0 or 8) */
    const int bl16 = lid & 15;
    const int brow = bl16 & 7;             /* B: row within n-tile */
    const int bcol8 = (bl16 >> 3) << 3;    /* B: k-half (0 or 8) */
    const int n0w = wid * 24;              /* warp's 24-col N slice */

    float xr[15];
    prefetch_x(x, blockIdx.x, tid, xr);

    for (int t = blockIdx.x; t < NTILES; t += GRID) {
        const int t0 = t * TOUT;

        /* stage x tile from prefetched regs: xs[d][c], c in [0,240) */
        #pragma unroll
        for (int j = 0; j < 15; j++) {
            int i = tid + j * THREADS;
            int d = i / XW, c = i - d * XW;
            xs[d * XSTR + c] = xr[j];
        }
        __syncthreads();

        /* build B (f16): B[j][col=16a+d] = xs[d][j+16a]; 8 cols -> one STS.128 */
        for (int i = tid; i < NROWS * 8; i += THREADS) {
            int j = i >> 3, g = i & 7;
            int a = g >> 1, d0 = (g & 1) * 8;
            const float* xp = xs + d0 * XSTR + (j + 16 * a);
            uint32_t hv[4];
            #pragma unroll
            for (int s = 0; s < 4; s++) {
                __half h0 = __float2half(xp[(2 * s) * XSTR]);
                __half h1 = __float2half(xp[(2 * s + 1) * XSTR]);
                hv[s] = (uint32_t)__half_as_ushort(h0) | ((uint32_t)__half_as_ushort(h1) << 16);
            }
            uint32_t off = SW128((uint32_t)(j * 128 + g * 16));
            *(uint4*)(smem + OFF_B + off) = make_uint4(hv[0], hv[1], hv[2], hv[3]);
        }
        __syncthreads();

        /* prefetch next tile's x (LDG latency hides under the MMA loop) */
        {
            int tn = t + GRID;
            prefetch_x(x, tn < NTILES ? tn : 0, tid, xr);
        }

        /* warp GEMM: Y'[0:128][n0w:n0w+24] = f16(P) x f16(x), single pass */
        float acc[8][3][4];
        #pragma unroll
        for (int mt = 0; mt < 8; mt++)
            #pragma unroll
            for (int nt = 0; nt < 3; nt++)
                #pragma unroll
                for (int r = 0; r < 4; r++) acc[mt][nt][r] = 0.f;

        {
            const uint32_t aBase = sbase + OFF_A;
            const uint32_t bBase = sbase + OFF_B;
            #pragma unroll
            for (int kc = 0; kc < 4; kc++) {
                const int k0 = kc * 16;
                uint32_t b0[3], b1[3];
                #pragma unroll
                for (int nt = 0; nt < 3; nt++) {
                    uint32_t off = (uint32_t)((n0w + nt * 8 + brow) * 128 + (k0 + bcol8) * 2);
                    ldsm_x2(b0[nt], b1[nt], bBase + SW128(off));
                }
                #pragma unroll
                for (int mt = 0; mt < 8; mt++) {
                    uint32_t a0, a1, a2, a3;
                    uint32_t off = (uint32_t)((mt * 16 + arow) * 128 + (k0 + acol8) * 2);
                    ldsm_x4(a0, a1, a2, a3, aBase + SW128(off));
                    #pragma unroll
                    for (int nt = 0; nt < 3; nt++)
                        mma16816(acc[mt][nt], a0, a1, a2, a3, b0[nt], b1[nt]);
                }
            }
        }

        __syncthreads();   /* B consumed; ys region (aliases xs) free to write */

        /* epilogue: fragments -> ys[m][j] */
        {
            const int quad = lid >> 2, ql = lid & 3;
            #pragma unroll
            for (int mt = 0; mt < 8; mt++) {
                #pragma unroll
                for (int nt = 0; nt < 3; nt++) {
                    int r0 = mt * 16 + quad;
                    int c0 = n0w + nt * 8 + ql * 2;
                    *(float2*)(ys + r0 * YSTR + c0)       = make_float2(acc[mt][nt][0], acc[mt][nt][1]);
                    *(float2*)(ys + (r0 + 8) * YSTR + c0) = make_float2(acc[mt][nt][2], acc[mt][nt][3]);
                }
            }
        }
        __syncthreads();

        /* diagonal b-sum: y[k, t0+u] = sum_b ys[k*16+b][u+b] */
        for (int o = tid; o < KN * TOUT; o += THREADS) {
            int k = o / TOUT, u = o - k * TOUT;
            if (t0 + u < LN) {
                const float* yb = ys + (k * 16) * YSTR + u;
                float s = 0.f;
                #pragma unroll
                for (int b = 0; b < 16; b++) s += yb[b * YSTR + b];
                out[(size_t)k * LN + t0 + u] = s;
            }
        }
        __syncthreads();
    }
}

/* exact reference boundary semantics in fp32 (overwrites first 31 / last 32 cols) */
__global__ void fullscan_boundary(const float* __restrict__ x, const float* __restrict__ P,
                                  float* __restrict__ out) {
    __shared__ float tl[KN][WN];
    __shared__ float tr[KN][WN];
    int tid = threadIdx.x;          /* 512 threads */
    int k = tid >> 6, m = tid & 63;
    float sl = 0.f, sr = 0.f;
    #pragma unroll
    for (int d = 0; d < DN; d++) {
        float p = P[k * (DN * WN) + d * WN + m];
        sl += x[(size_t)d * LN + m] * p;
        sr += x[(size_t)d * LN + (LN - WN) + m] * p;
    }
    tl[k][m] = sl; tr[k][m] = sr;
    __syncthreads();
    if (m < 31) {
        float s = 0.f;
        for (int mm = 0; mm <= 32 + m; mm++) s += tl[k][mm];
        out[(size_t)k * LN + m] = s;
    }
    if (m < 32) {
        float s = 0.f;
        for (int mm = m + 1; mm < WN; mm++) s += tr[k][mm];
        out[(size_t)k * LN + (LN - 32) + m] = s;
    }
}

extern "C" void kernel_launch(void* const* d_in, const int* in_sizes, int n_in,
                              void* d_out, int out_size) {
    const float* x = (const float*)d_in[0];
    const float* P = (const float*)d_in[1];
    float* out = (float*)d_out;

    cudaFuncSetAttribute(fullscan_mma, cudaFuncAttributeMaxDynamicSharedMemorySize, SMEM_BYTES);

    prep_A<<<32, 256>>>(P);
    fullscan_mma<<<GRID, THREADS, SMEM_BYTES>>>(x, out);
    fullscan_boundary<<<1, 512>>>(x, P, out);
}